// round 2
// baseline (speedup 1.0000x reference)
#include <cuda_runtime.h>
#include <cstdint>

#define GN 8192
#define GD 128
#define LMBD 0.1f

__device__ float g_main_part[GN];   // per-block partials (main + reg loss)

// ---------------------------------------------------------------------------
// Main kernel: one block per row of A (8192 blocks x 256 threads).
// Warp w owns columns [w*1024, (w+1)*1024). All 8 A-loads (float4, streaming)
// are front-batched for MLP=8. One ballot per float4; per active lane the 4
// components are broadcast and each nonzero triggers a warp-cooperative dot
// yi . (W[j]+b) with a 5-step butterfly reduce.
// Reg loss 0.5*lmbd*||Y[row]||^2 is computed by warp 0.
// ---------------------------------------------------------------------------
__global__ void __launch_bounds__(256, 4)
main_kernel(const float* __restrict__ A,
            const float* __restrict__ W,
            const float* __restrict__ b) {
    const int row  = blockIdx.x;
    const int w    = threadIdx.x >> 5;
    const int lane = threadIdx.x & 31;

    const float4* __restrict__ A4 =
        reinterpret_cast<const float4*>(A) + (size_t)row * (GN / 4);
    const float4* __restrict__ W4 = reinterpret_cast<const float4*>(W);

    const float4 b4 = reinterpret_cast<const float4*>(b)[lane];

    // Y[row]: lane holds elems [4*lane .. 4*lane+3]
    float4 yi = W4[row * 32 + lane];
    yi.x += b4.x; yi.y += b4.y; yi.z += b4.z; yi.w += b4.w;

    // Front-batched streaming loads of this warp's row segment (MLP = 8)
    const int base4 = w * 256;
    float4 av[8];
    #pragma unroll
    for (int k = 0; k < 8; k++)
        av[k] = __ldcs(A4 + base4 + k * 32 + lane);

    float acc = 0.f;   // identical on all lanes (everything is broadcast)

    #pragma unroll
    for (int k = 0; k < 8; k++) {
        float4 a4 = av[k];
        bool any = (a4.x > 0.f) | (a4.y > 0.f) | (a4.z > 0.f) | (a4.w > 0.f);
        unsigned m = __ballot_sync(0xffffffffu, any);

        while (m) {
            int src = __ffs(m) - 1;
            m &= m - 1;
            float ax = __shfl_sync(0xffffffffu, a4.x, src);
            float ay = __shfl_sync(0xffffffffu, a4.y, src);
            float az = __shfl_sync(0xffffffffu, a4.z, src);
            float aw = __shfl_sync(0xffffffffu, a4.w, src);
            const int jb = (base4 + k * 32 + src) * 4;  // column base

            #pragma unroll
            for (int e = 0; e < 4; e++) {
                float a = (e == 0) ? ax : (e == 1) ? ay : (e == 2) ? az : aw;
                if (a > 0.f) {   // warp-uniform branch
                    float4 yj = W4[(jb + e) * 32 + lane];
                    float p = (yj.x + b4.x) * yi.x + (yj.y + b4.y) * yi.y
                            + (yj.z + b4.z) * yi.z + (yj.w + b4.w) * yi.w;
                    p += __shfl_xor_sync(0xffffffffu, p, 16);
                    p += __shfl_xor_sync(0xffffffffu, p, 8);
                    p += __shfl_xor_sync(0xffffffffu, p, 4);
                    p += __shfl_xor_sync(0xffffffffu, p, 2);
                    p += __shfl_xor_sync(0xffffffffu, p, 1);
                    float r = a - p;
                    acc += 0.5f * r * r;
                }
            }
        }
    }

    // Reg loss for this row (warp 0): 0.5 * lmbd * sum(yi^2)
    float reg = 0.f;
    if (w == 0) {
        reg = yi.x * yi.x + yi.y * yi.y + yi.z * yi.z + yi.w * yi.w;
        reg += __shfl_xor_sync(0xffffffffu, reg, 16);
        reg += __shfl_xor_sync(0xffffffffu, reg, 8);
        reg += __shfl_xor_sync(0xffffffffu, reg, 4);
        reg += __shfl_xor_sync(0xffffffffu, reg, 2);
        reg += __shfl_xor_sync(0xffffffffu, reg, 1);
        reg *= 0.5f * LMBD;
    }

    __shared__ float s[8];
    if (lane == 0) s[w] = acc + reg;   // reg == 0 for w != 0
    __syncthreads();
    if (threadIdx.x == 0) {
        float t = 0.f;
        #pragma unroll
        for (int i = 0; i < 8; i++) t += s[i];
        g_main_part[row] = t;
    }
}

// ---------------------------------------------------------------------------
// Final reduction (single block, double accumulation)
// ---------------------------------------------------------------------------
__global__ void reduce_kernel(float* __restrict__ out) {
    double s = 0.0;
    for (int i = threadIdx.x; i < GN; i += 1024)
        s += (double)g_main_part[i];

    #pragma unroll
    for (int off = 16; off > 0; off >>= 1)
        s += __shfl_xor_sync(0xffffffffu, s, off);

    __shared__ double sd[32];
    int lane = threadIdx.x & 31;
    int w = threadIdx.x >> 5;
    if (lane == 0) sd[w] = s;
    __syncthreads();
    if (threadIdx.x == 0) {
        double t = 0.0;
        #pragma unroll
        for (int i = 0; i < 32; i++) t += sd[i];
        out[0] = (float)t;
    }
}

extern "C" void kernel_launch(void* const* d_in, const int* in_sizes, int n_in,
                              void* d_out, int out_size) {
    const float* A = (const float*)d_in[0];
    const float* W = (const float*)d_in[1];
    const float* b = (const float*)d_in[2];
    float* out = (float*)d_out;

    main_kernel<<<GN, 256>>>(A, W, b);
    reduce_kernel<<<1, 1024>>>(out);
}

// round 3
// speedup vs baseline: 1.2729x; 1.2729x over previous
#include <cuda_runtime.h>
#include <cstdint>

#define GN   8192
#define LMBD 0.1f
#define QCAP 64

__device__ float    g_sum;     // zero-initialized at load; reset by last block
__device__ unsigned g_count;

__device__ __forceinline__ float warp_dot(const float4 yi, const float4 b4,
                                          const float4 yj) {
    float p = (yj.x + b4.x) * yi.x + (yj.y + b4.y) * yi.y
            + (yj.z + b4.z) * yi.z + (yj.w + b4.w) * yi.w;
    p += __shfl_xor_sync(0xffffffffu, p, 16);
    p += __shfl_xor_sync(0xffffffffu, p, 8);
    p += __shfl_xor_sync(0xffffffffu, p, 4);
    p += __shfl_xor_sync(0xffffffffu, p, 2);
    p += __shfl_xor_sync(0xffffffffu, p, 1);
    return p;
}

// One block per row of A. Warp w owns cols [w*1024, (w+1)*1024) in 2 chunks of
// 4 float4-loads. Nonzeros are compacted into a per-warp smem queue, drained
// with a depth-2 pipelined warp-cooperative dot against L2-resident W.
__global__ void __launch_bounds__(256, 5)
main_kernel(const float* __restrict__ A, const float* __restrict__ W,
            const float* __restrict__ b, float* __restrict__ out) {
    __shared__ float qa[8][QCAP];
    __shared__ int   qj[8][QCAP];
    __shared__ float sp[8];

    const int row  = blockIdx.x;
    const int w    = threadIdx.x >> 5;
    const int lane = threadIdx.x & 31;

    const float4* __restrict__ A4 =
        reinterpret_cast<const float4*>(A) + (size_t)row * (GN / 4);
    const float4* __restrict__ W4 = reinterpret_cast<const float4*>(W);

    const float4 b4 = reinterpret_cast<const float4*>(b)[lane];
    float4 yi = W4[row * 32 + lane];
    yi.x += b4.x; yi.y += b4.y; yi.z += b4.z; yi.w += b4.w;

    const int base4 = w * 256;
    float acc0 = 0.f, acc1 = 0.f;   // identical on all lanes (all-broadcast)
    int cnt = 0;                     // warp-uniform queue count

    // compact one chunk (4 float4 groups) into the queue; cold overflow inline
    auto compact = [&](const float4* av, int coff) {
        #pragma unroll
        for (int k = 0; k < 4; k++) {
            const int g4 = base4 + coff + k * 32 + lane;
            #pragma unroll
            for (int e = 0; e < 4; e++) {
                float ae = (e == 0) ? av[k].x : (e == 1) ? av[k].y
                         : (e == 2) ? av[k].z : av[k].w;
                bool nz = ae > 0.f;
                unsigned m = __ballot_sync(0xffffffffu, nz);
                if (m) {
                    int pos = cnt + __popc(m & ((1u << lane) - 1));
                    if (nz && pos < QCAP) { qa[w][pos] = ae; qj[w][pos] = g4 * 4 + e; }
                    unsigned mo = __ballot_sync(0xffffffffu, nz && pos >= QCAP);
                    cnt = min(cnt + __popc(m), QCAP);
                    while (mo) {   // overflow fallback (never expected)
                        int src = __ffs(mo) - 1; mo &= mo - 1;
                        float a = __shfl_sync(0xffffffffu, ae, src);
                        int   j = __shfl_sync(0xffffffffu, g4 * 4 + e, src);
                        float4 yj = W4[j * 32 + lane];
                        float r = a - warp_dot(yi, b4, yj);
                        acc0 += 0.5f * r * r;
                    }
                }
            }
        }
    };

    // drain queue [from,to) with depth-2 prefetch pipeline
    auto drain = [&](int from, int to) {
        if (from >= to) return;
        int   j0 = qj[w][from];
        float a0 = qa[w][from];
        float4 y0 = W4[j0 * 32 + lane];
        for (int i = from; i < to; i++) {
            float4 y1 = y0; float a1 = 0.f;
            if (i + 1 < to) {
                int j = qj[w][i + 1];
                a1 = qa[w][i + 1];
                y1 = W4[j * 32 + lane];     // prefetch next while reducing cur
            }
            float r = a0 - warp_dot(yi, b4, y0);
            if ((i - from) & 1) acc1 += 0.5f * r * r;
            else                acc0 += 0.5f * r * r;
            y0 = y1; a0 = a1;
        }
    };

    float4 av[4];
    // chunk 0 loads (MLP=4, streaming)
    #pragma unroll
    for (int k = 0; k < 4; k++) av[k] = __ldcs(A4 + base4 + k * 32 + lane);
    compact(av, 0);
    int c0 = cnt;
    // issue chunk 1 loads BEFORE draining chunk 0 (overlap DRAM with dots)
    #pragma unroll
    for (int k = 0; k < 4; k++) av[k] = __ldcs(A4 + base4 + 128 + k * 32 + lane);
    drain(0, c0);
    compact(av, 128);
    drain(c0, cnt);

    float acc = acc0 + acc1;

    // reg loss for this row (warp 0 only): 0.5*lmbd*||yi||^2
    if (w == 0) {
        float reg = yi.x * yi.x + yi.y * yi.y + yi.z * yi.z + yi.w * yi.w;
        reg += __shfl_xor_sync(0xffffffffu, reg, 16);
        reg += __shfl_xor_sync(0xffffffffu, reg, 8);
        reg += __shfl_xor_sync(0xffffffffu, reg, 4);
        reg += __shfl_xor_sync(0xffffffffu, reg, 2);
        reg += __shfl_xor_sync(0xffffffffu, reg, 1);
        acc += 0.5f * LMBD * reg;
    }

    if (lane == 0) sp[w] = acc;
    __syncthreads();

    if (threadIdx.x == 0) {
        float part = 0.f;
        #pragma unroll
        for (int i = 0; i < 8; i++) part += sp[i];
        atomicAdd(&g_sum, part);
        __threadfence();
        unsigned c = atomicAdd(&g_count, 1u);
        if (c == gridDim.x - 1) {          // last block: publish + reset
            float total = atomicExch(&g_sum, 0.f);
            atomicExch(&g_count, 0u);
            out[0] = total;
        }
    }
}

extern "C" void kernel_launch(void* const* d_in, const int* in_sizes, int n_in,
                              void* d_out, int out_size) {
    const float* A = (const float*)d_in[0];
    const float* W = (const float*)d_in[1];
    const float* b = (const float*)d_in[2];
    float* out = (float*)d_out;

    main_kernel<<<GN, 256>>>(A, W, b, out);
}